// round 4
// baseline (speedup 1.0000x reference)
#include <cuda_runtime.h>
#include <cuda_fp16.h>
#include <math.h>
#include <stdint.h>

#define BB 16
#define TT 128
#define HH 1024
#define EE 1024
#define VV 32000
#define KK 2048                      // concat K for gates

// ---- K1 (LSTM HMMA) config ----
#define L_BLOCKS 64
#define L_THREADS 128
#define L_ROWS 64                    // gate rows per block (16 units x 4 gates)
#define L_NCHUNK 32                  // K chunks of 64
#define XPAD 2056                    // halves per x row
#define LWPAD 72

// smem offsets for k_lstm2 (bytes)
#define XHI_OFF  0                               // 16*2056*2 = 65792
#define XLO_OFF  65792                           // 65792
#define LWH0_OFF 131584                          // 64*72*2 = 9216
#define LWL0_OFF 140800
#define LWH1_OFF 150016
#define LWL1_OFF 159232
#define G4_OFF   168448                          // 64*17*4 = 4352
#define LTOK_OFF 172800                          // 16*4
#define L_SMEM   172928

// ---- K2 (logits) config ----
#define K2_ROWS   128
#define K2_BLOCKS (VV / K2_ROWS)     // 250
#define K2_THREADS 256
#define NCHUNK 16
#define TAU 0.05f
#define WPAD 72
#define HPAD 1032
#define LPAD 17

#define H_OFF    0
#define W0_OFF   33024
#define W1_OFF   51456
#define LOG_OFF  69888
#define THR_OFF  78592
#define CNT_OFF  78656
#define CAND_OFF 78672
#define K2_SMEM  79184

// -------- persistent scratch --------
__device__ float  g_h[2][BB * HH];
__device__ float  g_c[BB * HH];
__device__ __half g_h16[BB * HH];
__device__ __half g_W16[(size_t)VV * HH];        // 64 MB fp16 W_lin
__device__ __half g_Whi[(size_t)4 * HH * KK];    // 16.8 MB split gate weights (permuted)
__device__ __half g_Wlo[(size_t)4 * HH * KK];
__device__ float  g_pb[4 * HH];                  // permuted combined bias
__device__ unsigned long long g_amax[2][BB];
__device__ unsigned g_approx[2][BB];
__device__ float  g_pexp[TT][BB][K2_BLOCKS];

// ---------------- helpers ----------------
__device__ __forceinline__ unsigned ford(float f) {
    unsigned u = __float_as_uint(f);
    return (u & 0x80000000u) ? ~u : (u | 0x80000000u);
}
__device__ __forceinline__ float funord(unsigned v) {
    unsigned bits = (v & 0x80000000u) ? (v ^ 0x80000000u) : ~v;
    return __uint_as_float(bits);
}
#define CP16(dst, src)  asm volatile("cp.async.cg.shared.global [%0], [%1], 16;" :: "r"(dst), "l"(src) : "memory")
#define CP_COMMIT()     asm volatile("cp.async.commit_group;" ::: "memory")
#define CP_WAIT1()      asm volatile("cp.async.wait_group 1;" ::: "memory")
#define CP_WAIT0()      asm volatile("cp.async.wait_group 0;" ::: "memory")

__device__ __forceinline__ uint32_t smem_u32(const void* p) {
    uint32_t a;
    asm("{ .reg .u64 t; cvta.to.shared.u64 t, %1; cvt.u32.u64 %0, t; }" : "=r"(a) : "l"(p));
    return a;
}
__device__ __forceinline__ void mma16816(float* c, uint32_t a0, uint32_t a1,
                                         uint32_t a2, uint32_t a3,
                                         uint32_t b0, uint32_t b1) {
    asm volatile(
        "mma.sync.aligned.m16n8k16.row.col.f32.f16.f16.f32 "
        "{%0,%1,%2,%3}, {%4,%5,%6,%7}, {%8,%9}, {%0,%1,%2,%3};"
        : "+f"(c[0]), "+f"(c[1]), "+f"(c[2]), "+f"(c[3])
        : "r"(a0), "r"(a1), "r"(a2), "r"(a3), "r"(b0), "r"(b1));
}

// ---------------------------------------------------------------------
__global__ void k_init(const float* __restrict__ h0, const float* __restrict__ c0,
                       const float* __restrict__ bih, const float* __restrict__ bhh) {
    int i = blockIdx.x * blockDim.x + threadIdx.x;
    if (i < BB * HH) {
        g_h[0][i] = h0[i];
        g_c[i]    = c0[i];
    }
    if (i < BB) g_amax[0][i] = (unsigned long long)(~1u);   // SOS = 1
    if (i < 4 * HH) {
        int j = i >> 2, g = i & 3;
        int orig = g * HH + j;
        g_pb[i] = bih[orig] + bhh[orig];
    }
}

// W_lin fp32 -> fp16
__global__ void k_cvt(const float* __restrict__ W) {
    size_t i = ((size_t)blockIdx.x * 256 + threadIdx.x) * 8;
    float4 a = *(const float4*)(W + i);
    float4 b = *(const float4*)(W + i + 4);
    __half2 p0 = __floats2half2_rn(a.x, a.y), p1 = __floats2half2_rn(a.z, a.w);
    __half2 p2 = __floats2half2_rn(b.x, b.y), p3 = __floats2half2_rn(b.z, b.w);
    uint4 o;
    o.x = *(uint32_t*)&p0; o.y = *(uint32_t*)&p1;
    o.z = *(uint32_t*)&p2; o.w = *(uint32_t*)&p3;
    *(uint4*)(g_W16 + i) = o;
}

// gate weights -> split fp16, permuted rows (new_row = unit*4 + gate), K = [Wih | Whh]
__global__ void k_cvt2(const float* __restrict__ Wih, const float* __restrict__ Whh) {
    size_t idx = ((size_t)blockIdx.x * 256 + threadIdx.x) * 8;
    int nr = (int)(idx >> 11);
    int k  = (int)(idx & 2047);
    int j = nr >> 2, g = nr & 3;
    int orig = g * HH + j;
    const float* src = (k < HH) ? (Wih + (size_t)orig * HH + k)
                                : (Whh + (size_t)orig * HH + (k - HH));
    __half hi8[8], lo8[8];
#pragma unroll
    for (int q = 0; q < 8; q++) {
        float v = src[q];
        __half h = __float2half_rn(v);
        hi8[q] = h;
        lo8[q] = __float2half_rn(v - __half2float(h));
    }
    *(uint4*)(g_Whi + idx) = *(uint4*)hi8;
    *(uint4*)(g_Wlo + idx) = *(uint4*)lo8;
}

// ---------------------------------------------------------------------
// K1 v2: split-fp16 HMMA gate GEMM + in-block LSTM pointwise.
// 64 blocks x 128 threads; block owns 64 permuted gate rows = 16 units.
__global__ void __launch_bounds__(L_THREADS)
k_lstm2(int t, const float* __restrict__ emb) {
    extern __shared__ char sm[];
    const uint32_t smem_base = smem_u32(sm);
    __half* xhi = (__half*)(sm + XHI_OFF);
    __half* xlo = (__half*)(sm + XLO_OFF);
    float*  g4  = (float*)(sm + G4_OFF);
    int*    tok_s = (int*)(sm + LTOK_OFF);

    const int tid = threadIdx.x, warp = tid >> 5, lane = tid & 31;
    const int r = lane >> 2, q4 = lane & 3;
    const int pr  = t & 1;
    const int cur = (t + 1) & 1;

    if (tid < BB) tok_s[tid] = (int)(~(unsigned)g_amax[pr][tid]);
    if (blockIdx.x == 0 && tid < BB) { g_amax[cur][tid] = 0ull; g_approx[cur][tid] = 0u; }
    __syncthreads();

    // prefetch W chunk 0 (hi + lo)
    const size_t wbase = (size_t)blockIdx.x * L_ROWS * KK;
#pragma unroll
    for (int q = 0; q < 4; q++) {
        int i = tid + q * 128;               // 512 cp16 per array
        int row = i >> 3, col16 = i & 7;
        size_t src = wbase + (size_t)row * KK + col16 * 8;
        CP16(smem_base + LWH0_OFF + (uint32_t)(row * LWPAD + col16 * 8) * 2, g_Whi + src);
        CP16(smem_base + LWL0_OFF + (uint32_t)(row * LWPAD + col16 * 8) * 2, g_Wlo + src);
    }
    CP_COMMIT();

    // build split x = [emb[tok]; h] in smem: [16][XPAD] hi/lo
    for (int q = 0; q < 64; q++) {
        int i4 = tid + q * 128;              // float4 index over 8192
        int b  = i4 >> 9;                    // 512 float4 per batch row
        int k  = (i4 & 511) << 2;
        float4 v;
        if (k < EE) v = *(const float4*)(emb + (size_t)tok_s[b] * EE + k);
        else        v = *(const float4*)(g_h[pr] + b * HH + (k - EE));
        __half h0 = __float2half_rn(v.x), h1 = __float2half_rn(v.y);
        __half h2 = __float2half_rn(v.z), h3 = __float2half_rn(v.w);
        __half l0 = __float2half_rn(v.x - __half2float(h0));
        __half l1 = __float2half_rn(v.y - __half2float(h1));
        __half l2 = __float2half_rn(v.z - __half2float(h2));
        __half l3 = __float2half_rn(v.w - __half2float(h3));
        __half hi4[4] = {h0, h1, h2, h3};
        __half lo4[4] = {l0, l1, l2, l3};
        *(uint2*)(xhi + b * XPAD + k) = *(uint2*)hi4;
        *(uint2*)(xlo + b * XPAD + k) = *(uint2*)lo4;
    }

    float acc0[4] = {0.f, 0.f, 0.f, 0.f};
    float acc1[4] = {0.f, 0.f, 0.f, 0.f};

    for (int c = 0; c < L_NCHUNK; c++) {
        if (c + 1 < L_NCHUNK) {
            uint32_t oh = ((c + 1) & 1) ? LWH1_OFF : LWH0_OFF;
            uint32_t ol = ((c + 1) & 1) ? LWL1_OFF : LWL0_OFF;
#pragma unroll
            for (int q = 0; q < 4; q++) {
                int i = tid + q * 128;
                int row = i >> 3, col16 = i & 7;
                size_t src = wbase + (size_t)row * KK + (c + 1) * 64 + col16 * 8;
                CP16(smem_base + oh + (uint32_t)(row * LWPAD + col16 * 8) * 2, g_Whi + src);
                CP16(smem_base + ol + (uint32_t)(row * LWPAD + col16 * 8) * 2, g_Wlo + src);
            }
            CP_COMMIT();
            CP_WAIT1();
        } else {
            CP_WAIT0();
        }
        __syncthreads();

        const __half* wh = (const __half*)(sm + ((c & 1) ? LWH1_OFF : LWH0_OFF));
        const __half* wl = (const __half*)(sm + ((c & 1) ? LWL1_OFF : LWL0_OFF));
        const int kbase = c * 64;
#pragma unroll
        for (int ks = 0; ks < 4; ks++) {
            int k0 = ks * 16 + q4 * 2;
            int kg = kbase + k0;
            const int ra = (warp * 16 + r) * LWPAD;
            const int rb = (warp * 16 + r + 8) * LWPAD;
            uint32_t ah0 = *(const uint32_t*)(wh + ra + k0);
            uint32_t ah1 = *(const uint32_t*)(wh + rb + k0);
            uint32_t ah2 = *(const uint32_t*)(wh + ra + k0 + 8);
            uint32_t ah3 = *(const uint32_t*)(wh + rb + k0 + 8);
            uint32_t al0 = *(const uint32_t*)(wl + ra + k0);
            uint32_t al1 = *(const uint32_t*)(wl + rb + k0);
            uint32_t al2 = *(const uint32_t*)(wl + ra + k0 + 8);
            uint32_t al3 = *(const uint32_t*)(wl + rb + k0 + 8);

            uint32_t bh00 = *(const uint32_t*)(xhi + r * XPAD + kg);
            uint32_t bh01 = *(const uint32_t*)(xhi + r * XPAD + kg + 8);
            uint32_t bh10 = *(const uint32_t*)(xhi + (r + 8) * XPAD + kg);
            uint32_t bh11 = *(const uint32_t*)(xhi + (r + 8) * XPAD + kg + 8);
            uint32_t bl00 = *(const uint32_t*)(xlo + r * XPAD + kg);
            uint32_t bl01 = *(const uint32_t*)(xlo + r * XPAD + kg + 8);
            uint32_t bl10 = *(const uint32_t*)(xlo + (r + 8) * XPAD + kg);
            uint32_t bl11 = *(const uint32_t*)(xlo + (r + 8) * XPAD + kg + 8);

            mma16816(acc0, ah0, ah1, ah2, ah3, bh00, bh01);   // Whi*xhi
            mma16816(acc0, ah0, ah1, ah2, ah3, bl00, bl01);   // Whi*xlo
            mma16816(acc0, al0, al1, al2, al3, bh00, bh01);   // Wlo*xhi
            mma16816(acc1, ah0, ah1, ah2, ah3, bh10, bh11);
            mma16816(acc1, ah0, ah1, ah2, ah3, bl10, bl11);
            mma16816(acc1, al0, al1, al2, al3, bh10, bh11);
        }
        __syncthreads();
    }

    // stage gates to smem [64 rows][17]
    {
        int lr0 = warp * 16 + r, lr1 = lr0 + 8;
        int c0 = q4 * 2;
        g4[lr0 * 17 + c0]     = acc0[0];
        g4[lr0 * 17 + c0 + 1] = acc0[1];
        g4[lr1 * 17 + c0]     = acc0[2];
        g4[lr1 * 17 + c0 + 1] = acc0[3];
        g4[lr0 * 17 + c0 + 8]     = acc1[0];
        g4[lr0 * 17 + c0 + 9]     = acc1[1];
        g4[lr1 * 17 + c0 + 8]     = acc1[2];
        g4[lr1 * 17 + c0 + 9]     = acc1[3];
    }
    __syncthreads();

    // LSTM pointwise: 16 units x 16 batches = 256 pairs, 2 per thread
#pragma unroll
    for (int pp = 0; pp < 2; pp++) {
        int p = tid + pp * 128;
        int unitloc = p >> 4, b = p & 15;
        int lr = unitloc * 4;
        int nrb = blockIdx.x * L_ROWS + lr;
        float gi = g4[(lr + 0) * 17 + b] + g_pb[nrb + 0];
        float gf = g4[(lr + 1) * 17 + b] + g_pb[nrb + 1];
        float gg = g4[(lr + 2) * 17 + b] + g_pb[nrb + 2];
        float go = g4[(lr + 3) * 17 + b] + g_pb[nrb + 3];
        int j = blockIdx.x * 16 + unitloc;
        float si = 1.f / (1.f + expf(-gi));
        float sf = 1.f / (1.f + expf(-gf));
        float so = 1.f / (1.f + expf(-go));
        float cc = sf * g_c[b * HH + j] + si * tanhf(gg);
        g_c[b * HH + j] = cc;
        float h = so * tanhf(cc);
        g_h[cur][b * HH + j] = h;
        g_h16[b * HH + j] = __float2half(h);
    }
}

// ---------------------------------------------------------------------
// K2: fp16 HMMA logits GEMM + epilogue + exact fp32 argmax rescue (unchanged from R3)
__global__ void __launch_bounds__(K2_THREADS)
k_logits(int t, const float* __restrict__ Wlin, const float* __restrict__ blin,
         float* __restrict__ out) {
    extern __shared__ char sm[];
    const uint32_t smem_base = smem_u32(sm);
    __half* h_s   = (__half*)(sm + H_OFF);
    float*  log_s = (float*)(sm + LOG_OFF);
    float*  thr_s = (float*)(sm + THR_OFF);
    int*    cnt_s = (int*)(sm + CNT_OFF);
    int*    cand_s = (int*)(sm + CAND_OFF);

    const int tid = threadIdx.x, warp = tid >> 5, lane = tid & 31;
    const int cur = (t + 1) & 1;
    const int r = lane >> 2, q4 = lane & 3;

    if (tid == 0) *cnt_s = 0;

#pragma unroll
    for (int q = 0; q < 8; q++) {
        int i = tid + q * 256;
        int b = i >> 7, k8 = i & 127;
        float4 v = *(const float4*)(g_h16 + (size_t)b * HH + k8 * 8);
        *(float4*)(h_s + b * HPAD + k8 * 8) = v;
    }

    const size_t wrow_base = (size_t)blockIdx.x * K2_ROWS * HH;
#pragma unroll
    for (int qq = 0; qq < 4; qq++) {
        int i = tid + qq * 256;
        int row = i >> 3, col16 = i & 7;
        CP16(smem_base + W0_OFF + (uint32_t)(row * WPAD + col16 * 8) * 2,
             g_W16 + wrow_base + (size_t)row * HH + col16 * 8);
    }
    CP_COMMIT();

    float acc0[4] = {0.f, 0.f, 0.f, 0.f};
    float acc1[4] = {0.f, 0.f, 0.f, 0.f};

    for (int c = 0; c < NCHUNK; c++) {
        if (c + 1 < NCHUNK) {
            uint32_t wb_off = ((c + 1) & 1) ? W1_OFF : W0_OFF;
#pragma unroll
            for (int qq = 0; qq < 4; qq++) {
                int i = tid + qq * 256;
                int row = i >> 3, col16 = i & 7;
                CP16(smem_base + wb_off + (uint32_t)(row * WPAD + col16 * 8) * 2,
                     g_W16 + wrow_base + (size_t)row * HH + (c + 1) * 64 + col16 * 8);
            }
            CP_COMMIT();
            CP_WAIT1();
        } else {
            CP_WAIT0();
        }
        __syncthreads();

        const __half* wb = (const __half*)(sm + ((c & 1) ? W1_OFF : W0_OFF));
        const int kbase = c * 64;
#pragma unroll
        for (int ks = 0; ks < 4; ks++) {
            int k0 = ks * 16 + q4 * 2;
            uint32_t a0 = *(const uint32_t*)(wb + (warp * 16 + r) * WPAD + k0);
            uint32_t a1 = *(const uint32_t*)(wb + (warp * 16 + r + 8) * WPAD + k0);
            uint32_t a2 = *(const uint32_t*)(wb + (warp * 16 + r) * WPAD + k0 + 8);
            uint32_t a3 = *(const uint32_t*)(wb + (warp * 16 + r + 8) * WPAD + k0 + 8);
            int kg = kbase + k0;
            uint32_t b00 = *(const uint32_t*)(h_s + r * HPAD + kg);
            uint32_t b01 = *(const uint32_t*)(h_s + r * HPAD + kg + 8);
            uint32_t b10 = *(const uint32_t*)(h_s + (r + 8) * HPAD + kg);
            uint32_t b11 = *(const uint32_t*)(h_s + (r + 8) * HPAD + kg + 8);
            mma16816(acc0, a0, a1, a2, a3, b00, b01);
            mma16816(acc1, a0, a1, a2, a3, b10, b11);
        }
        __syncthreads();
    }

    {
        const int rbase = warp * 16 + r;
        const float bl0 = blin[blockIdx.x * K2_ROWS + rbase];
        const float bl1 = blin[blockIdx.x * K2_ROWS + rbase + 8];
        const int c0 = q4 * 2;
        log_s[rbase * LPAD + c0]           = acc0[0] + bl0;
        log_s[rbase * LPAD + c0 + 1]       = acc0[1] + bl0;
        log_s[(rbase + 8) * LPAD + c0]     = acc0[2] + bl1;
        log_s[(rbase + 8) * LPAD + c0 + 1] = acc0[3] + bl1;
        log_s[rbase * LPAD + c0 + 8]       = acc1[0] + bl0;
        log_s[rbase * LPAD + c0 + 9]       = acc1[1] + bl0;
        log_s[(rbase + 8) * LPAD + c0 + 8] = acc1[2] + bl1;
        log_s[(rbase + 8) * LPAD + c0 + 9] = acc1[3] + bl1;
    }
    __syncthreads();

#pragma unroll
    for (int i = 0; i < 8; i++) {
        int idx = tid + i * 256;
        int row = idx & 127, b = idx >> 7;
        out[(size_t)b * TT * VV + (size_t)t * VV + blockIdx.x * K2_ROWS + row] =
            log_s[row * LPAD + b];
    }

    {
        int b = 2 * warp + (lane >> 4);
        int l = lane & 15;
        float s = 0.f, m = -1e30f;
#pragma unroll
        for (int rr = 0; rr < 8; rr++) {
            float v = log_s[(l * 8 + rr) * LPAD + b];
            s += expf(v);
            m = fmaxf(m, v);
        }
#pragma unroll
        for (int off = 8; off; off >>= 1) {
            s += __shfl_xor_sync(0xFFFFFFFFu, s, off);
            m = fmaxf(m, __shfl_xor_sync(0xFFFFFFFFu, m, off));
        }
        if (l == 0) {
            g_pexp[t][b][blockIdx.x] = s;
            unsigned fm = ford(m);
            unsigned old = atomicMax(&g_approx[cur][b], fm);
            unsigned L = old > fm ? old : fm;
            thr_s[b] = funord(L) - TAU;
        }
    }
    __syncthreads();

#pragma unroll
    for (int i = 0; i < 8; i++) {
        int idx = tid + i * 256;
        int row = idx & 127, b = idx >> 7;
        if (log_s[row * LPAD + b] >= thr_s[b]) {
            int slot = atomicAdd(cnt_s, 1);
            if (slot < 128) cand_s[slot] = ((blockIdx.x * K2_ROWS + row) << 4) | b;
        }
    }
    __syncthreads();

    int n = *cnt_s; if (n > 128) n = 128;
    for (int e = warp; e < n; e += 8) {
        int pk = cand_s[e];
        int rr = pk >> 4, b = pk & 15;
        const float4* Wr = (const float4*)(Wlin + (size_t)rr * HH);
        const float4* hr = (const float4*)(g_h[cur] + b * HH);
        float acc = 0.f;
#pragma unroll
        for (int qq = 0; qq < 8; qq++) {
            float4 w = Wr[lane + qq * 32];
            float4 h = hr[lane + qq * 32];
            acc += w.x * h.x + w.y * h.y + w.z * h.z + w.w * h.w;
        }
#pragma unroll
        for (int off = 16; off; off >>= 1) acc += __shfl_xor_sync(0xFFFFFFFFu, acc, off);
        if (lane == 0) {
            float ex = acc + blin[rr];
            unsigned long long pkd =
                ((unsigned long long)ford(ex) << 32) | (unsigned)(~(unsigned)rr);
            atomicMax(&g_amax[cur][b], pkd);
        }
    }
}

// ---------------------------------------------------------------------
__global__ void k_final(float* __restrict__ out) {
    const int t = blockIdx.x >> 4;
    const int b = blockIdx.x & 15;
    __shared__ float red[256];
    float s = 0.f;
    for (int i = threadIdx.x; i < K2_BLOCKS; i += 256) s += g_pexp[t][b][i];
    red[threadIdx.x] = s;
    __syncthreads();
    for (int off = 128; off; off >>= 1) {
        if (threadIdx.x < off) red[threadIdx.x] += red[threadIdx.x + off];
        __syncthreads();
    }
    const float lse = logf(red[0]);
    float* p = out + (size_t)b * TT * VV + (size_t)t * VV;
    for (int i = threadIdx.x; i < VV / 4; i += 256) {
        float4 v = *(float4*)(p + i * 4);
        v.x -= lse; v.y -= lse; v.z -= lse; v.w -= lse;
        *(float4*)(p + i * 4) = v;
    }
}

__global__ void k_hc(float* __restrict__ out) {
    int i = blockIdx.x * blockDim.x + threadIdx.x;
    if (i < BB * HH) {
        out[(size_t)BB * TT * VV + i]           = g_h[0][i];
        out[(size_t)BB * TT * VV + BB * HH + i] = g_c[i];
    }
}

// ---------------------------------------------------------------------
extern "C" void kernel_launch(void* const* d_in, const int* in_sizes, int n_in,
                              void* d_out, int out_size) {
    const float* h0   = (const float*)d_in[1];
    const float* c0   = (const float*)d_in[2];
    const float* emb  = (const float*)d_in[3];
    const float* Wih  = (const float*)d_in[4];
    const float* Whh  = (const float*)d_in[5];
    const float* bih  = (const float*)d_in[6];
    const float* bhh  = (const float*)d_in[7];
    const float* Wlin = (const float*)d_in[8];
    const float* blin = (const float*)d_in[9];
    float* out = (float*)d_out;

    cudaFuncSetAttribute(k_logits, cudaFuncAttributeMaxDynamicSharedMemorySize, K2_SMEM);
    cudaFuncSetAttribute(k_lstm2, cudaFuncAttributeMaxDynamicSharedMemorySize, L_SMEM);

    k_init<<<(BB * HH + 255) / 256, 256>>>(h0, c0, bih, bhh);
    k_cvt<<<(int)((size_t)VV * HH / 8 / 256), 256>>>(Wlin);
    k_cvt2<<<(int)((size_t)4 * HH * KK / 8 / 256), 256>>>(Wih, Whh);
    for (int t = 0; t < TT; t++) {
        k_lstm2<<<L_BLOCKS, L_THREADS, L_SMEM>>>(t, emb);
        k_logits<<<K2_BLOCKS, K2_THREADS, K2_SMEM>>>(t, Wlin, blin, out);
    }
    k_final<<<TT * BB, 256>>>(out);
    k_hc<<<(BB * HH + 255) / 256, 256>>>(out);
}

// round 5
// speedup vs baseline: 1.1406x; 1.1406x over previous
#include <cuda_runtime.h>
#include <cuda_fp16.h>
#include <math.h>
#include <stdint.h>

#define BB 16
#define TT 128
#define HH 1024
#define EE 1024
#define VV 32000
#define KK 2048

// ---- K1 (LSTM HMMA) config ----
#define L_BLOCKS 128
#define L_THREADS 256
#define L_ROWS 32                    // gate rows per block (8 units x 4 gates)
#define L_NCHUNK 32                  // K chunks of 64
#define XPAD 2056
#define LWPAD 72

// smem offsets for k_lstm3 (bytes)
#define XHI_OFF  0                               // 16*2056*2 = 65792
#define XLO_OFF  65792
#define LWH0_OFF 131584                          // 32*72*2 = 4608
#define LWL0_OFF 136192
#define LWH1_OFF 140800
#define LWL1_OFF 145408
#define G4_OFF   150016                          // 32*17*4 = 2176
#define RED_OFF  152192                          // 4*32*4*4 = 2048
#define L_SMEM   154240

// ---- K2 (logits) config ----
#define K2_ROWS   128
#define K2_BLOCKS (VV / K2_ROWS)     // 250
#define K2_THREADS 256
#define NCHUNK 16
#define TAU 0.05f
#define WPAD 72
#define HPAD 1032
#define LPAD 17

#define H_OFF    0
#define W0_OFF   33024
#define W1_OFF   51456
#define LOG_OFF  69888
#define THR_OFF  78592
#define CNT_OFF  78656
#define CAND_OFF 78672
#define K2_SMEM  79184

// -------- persistent scratch --------
__device__ float  g_h[2][BB * HH];
__device__ float  g_c[BB * HH];
__device__ __half g_h16[BB * HH];
__device__ __half g_W16[(size_t)VV * HH];        // 64 MB fp16 W_lin
__device__ __half g_Whi[(size_t)4 * HH * KK];    // split gate weights (permuted rows)
__device__ __half g_Wlo[(size_t)4 * HH * KK];
__device__ __half g_xhi[BB * KK];                // per-step split x = [emb; h]
__device__ __half g_xlo[BB * KK];
__device__ float  g_pb[4 * HH];
__device__ unsigned long long g_amax[2][BB];
__device__ unsigned g_approx[2][BB];
__device__ float  g_pexp[TT][BB][K2_BLOCKS];

// ---------------- helpers ----------------
__device__ __forceinline__ unsigned ford(float f) {
    unsigned u = __float_as_uint(f);
    return (u & 0x80000000u) ? ~u : (u | 0x80000000u);
}
__device__ __forceinline__ float funord(unsigned v) {
    unsigned bits = (v & 0x80000000u) ? (v ^ 0x80000000u) : ~v;
    return __uint_as_float(bits);
}
#define CP16(dst, src)  asm volatile("cp.async.cg.shared.global [%0], [%1], 16;" :: "r"(dst), "l"(src) : "memory")
#define CP_COMMIT()     asm volatile("cp.async.commit_group;" ::: "memory")
#define CP_WAIT1()      asm volatile("cp.async.wait_group 1;" ::: "memory")
#define CP_WAIT0()      asm volatile("cp.async.wait_group 0;" ::: "memory")

__device__ __forceinline__ uint32_t smem_u32(const void* p) {
    uint32_t a;
    asm("{ .reg .u64 t; cvta.to.shared.u64 t, %1; cvt.u32.u64 %0, t; }" : "=r"(a) : "l"(p));
    return a;
}
__device__ __forceinline__ void mma16816(float* c, uint32_t a0, uint32_t a1,
                                         uint32_t a2, uint32_t a3,
                                         uint32_t b0, uint32_t b1) {
    asm volatile(
        "mma.sync.aligned.m16n8k16.row.col.f32.f16.f16.f32 "
        "{%0,%1,%2,%3}, {%4,%5,%6,%7}, {%8,%9}, {%0,%1,%2,%3};"
        : "+f"(c[0]), "+f"(c[1]), "+f"(c[2]), "+f"(c[3])
        : "r"(a0), "r"(a1), "r"(a2), "r"(a3), "r"(b0), "r"(b1));
}

// ---------------------------------------------------------------------
__global__ void k_init(const float* __restrict__ h0, const float* __restrict__ c0,
                       const float* __restrict__ bih, const float* __restrict__ bhh) {
    int i = blockIdx.x * blockDim.x + threadIdx.x;
    if (i < BB * HH) {
        g_h[0][i] = h0[i];
        g_c[i]    = c0[i];
    }
    if (i < BB) g_amax[0][i] = (unsigned long long)(~1u);   // SOS = 1
    if (i < 4 * HH) {
        int j = i >> 2, g = i & 3;
        int orig = g * HH + j;
        g_pb[i] = bih[orig] + bhh[orig];
    }
}

__global__ void k_cvt(const float* __restrict__ W) {
    size_t i = ((size_t)blockIdx.x * 256 + threadIdx.x) * 8;
    float4 a = *(const float4*)(W + i);
    float4 b = *(const float4*)(W + i + 4);
    __half2 p0 = __floats2half2_rn(a.x, a.y), p1 = __floats2half2_rn(a.z, a.w);
    __half2 p2 = __floats2half2_rn(b.x, b.y), p3 = __floats2half2_rn(b.z, b.w);
    uint4 o;
    o.x = *(uint32_t*)&p0; o.y = *(uint32_t*)&p1;
    o.z = *(uint32_t*)&p2; o.w = *(uint32_t*)&p3;
    *(uint4*)(g_W16 + i) = o;
}

// gate weights -> split fp16, permuted rows (new_row = unit*4 + gate), K = [Wih | Whh]
__global__ void k_cvt2(const float* __restrict__ Wih, const float* __restrict__ Whh) {
    size_t idx = ((size_t)blockIdx.x * 256 + threadIdx.x) * 8;
    int nr = (int)(idx >> 11);
    int k  = (int)(idx & 2047);
    int j = nr >> 2, g = nr & 3;
    int orig = g * HH + j;
    const float* src = (k < HH) ? (Wih + (size_t)orig * HH + k)
                                : (Whh + (size_t)orig * HH + (k - HH));
    __half hi8[8], lo8[8];
#pragma unroll
    for (int q = 0; q < 8; q++) {
        float v = src[q];
        __half h = __float2half_rn(v);
        hi8[q] = h;
        lo8[q] = __float2half_rn(v - __half2float(h));
    }
    *(uint4*)(g_Whi + idx) = *(uint4*)hi8;
    *(uint4*)(g_Wlo + idx) = *(uint4*)lo8;
}

// ---------------------------------------------------------------------
// per-step: gather x = [emb[tok]; h], split into fp16 hi/lo planes (once)
__global__ void k_xsplit(int t, const float* __restrict__ emb) {
    const int pr  = t & 1;
    const int cur = (t + 1) & 1;
    int i4 = blockIdx.x * blockDim.x + threadIdx.x;      // 8192 float4
    int b = i4 >> 9, k = (i4 & 511) << 2;
    int tok = (int)(~(unsigned)g_amax[pr][b]);
    float4 v;
    if (k < EE) v = *(const float4*)(emb + (size_t)tok * EE + k);
    else        v = *(const float4*)(g_h[pr] + b * HH + (k - EE));
    __half h0 = __float2half_rn(v.x), h1 = __float2half_rn(v.y);
    __half h2 = __float2half_rn(v.z), h3 = __float2half_rn(v.w);
    __half l0 = __float2half_rn(v.x - __half2float(h0));
    __half l1 = __float2half_rn(v.y - __half2float(h1));
    __half l2 = __float2half_rn(v.z - __half2float(h2));
    __half l3 = __float2half_rn(v.w - __half2float(h3));
    __half hi4[4] = {h0, h1, h2, h3};
    __half lo4[4] = {l0, l1, l2, l3};
    *(uint2*)(g_xhi + b * KK + k) = *(uint2*)hi4;
    *(uint2*)(g_xlo + b * KK + k) = *(uint2*)lo4;
    if (i4 < BB) { g_amax[cur][i4] = 0ull; g_approx[cur][i4] = 0u; }
}

// ---------------------------------------------------------------------
// K1 v3: split-fp16 HMMA gate GEMM. 128 blocks x 256 threads, 32 rows/block.
// 8 warps = 4 (m16,n8) quadrants x 2-way K split; smem reduce; in-block pointwise.
__global__ void __launch_bounds__(L_THREADS)
k_lstm3(int t) {
    extern __shared__ char sm[];
    const uint32_t smem_base = smem_u32(sm);
    __half* xhi = (__half*)(sm + XHI_OFF);
    __half* xlo = (__half*)(sm + XLO_OFF);
    float*  g4  = (float*)(sm + G4_OFF);
    float*  red = (float*)(sm + RED_OFF);

    const int tid = threadIdx.x, warp = tid >> 5, lane = tid & 31;
    const int r = lane >> 2, q4 = lane & 3;
    const int quad = warp & 3, kh = warp >> 2;
    const int mrow_base = (quad >> 1) * 16;       // 0 or 16
    const int nb_base   = (quad & 1) * 8;         // batch 0 or 8
    const int cur = (t + 1) & 1;

    // cp.async x hi/lo into smem (group 0): 4096 cp16 per array
#pragma unroll
    for (int q = 0; q < 16; q++) {
        int i = tid + q * 256;
        int b = i >> 8, k8 = i & 255;             // 256 cp16 per batch row
        CP16(smem_base + XHI_OFF + (uint32_t)(b * XPAD + k8 * 8) * 2, g_xhi + b * KK + k8 * 8);
        CP16(smem_base + XLO_OFF + (uint32_t)(b * XPAD + k8 * 8) * 2, g_xlo + b * KK + k8 * 8);
    }
    CP_COMMIT();

    // W chunk 0 (hi+lo): 256 cp16 each
    const size_t wbase = (size_t)blockIdx.x * L_ROWS * KK;
#pragma unroll
    for (int q = 0; q < 1; q++) {
        int i = tid;                               // 256 = 32 rows x 8 col16
        int row = i >> 3, col16 = i & 7;
        size_t src = wbase + (size_t)row * KK + col16 * 8;
        CP16(smem_base + LWH0_OFF + (uint32_t)(row * LWPAD + col16 * 8) * 2, g_Whi + src);
        CP16(smem_base + LWL0_OFF + (uint32_t)(row * LWPAD + col16 * 8) * 2, g_Wlo + src);
    }
    CP_COMMIT();

    float acc[4] = {0.f, 0.f, 0.f, 0.f};

    for (int c = 0; c < L_NCHUNK; c++) {
        if (c + 1 < L_NCHUNK) {
            uint32_t oh = ((c + 1) & 1) ? LWH1_OFF : LWH0_OFF;
            uint32_t ol = ((c + 1) & 1) ? LWL1_OFF : LWL0_OFF;
            int row = tid >> 3, col16 = tid & 7;
            size_t src = wbase + (size_t)row * KK + (c + 1) * 64 + col16 * 8;
            CP16(smem_base + oh + (uint32_t)(row * LWPAD + col16 * 8) * 2, g_Whi + src);
            CP16(smem_base + ol + (uint32_t)(row * LWPAD + col16 * 8) * 2, g_Wlo + src);
            CP_COMMIT();
            CP_WAIT1();
        } else {
            CP_WAIT0();
        }
        __syncthreads();

        const __half* wh = (const __half*)(sm + ((c & 1) ? LWH1_OFF : LWH0_OFF));
        const __half* wl = (const __half*)(sm + ((c & 1) ? LWL1_OFF : LWL0_OFF));
#pragma unroll
        for (int ks = 0; ks < 2; ks++) {
            int k_local = kh * 32 + ks * 16 + q4 * 2;     // within chunk
            int kg = c * 64 + k_local;                    // within full K
            const int ra = (mrow_base + r) * LWPAD;
            const int rb = (mrow_base + r + 8) * LWPAD;
            uint32_t ah0 = *(const uint32_t*)(wh + ra + k_local);
            uint32_t ah1 = *(const uint32_t*)(wh + rb + k_local);
            uint32_t ah2 = *(const uint32_t*)(wh + ra + k_local + 8);
            uint32_t ah3 = *(const uint32_t*)(wh + rb + k_local + 8);
            uint32_t al0 = *(const uint32_t*)(wl + ra + k_local);
            uint32_t al1 = *(const uint32_t*)(wl + rb + k_local);
            uint32_t al2 = *(const uint32_t*)(wl + ra + k_local + 8);
            uint32_t al3 = *(const uint32_t*)(wl + rb + k_local + 8);

            const int xb = (nb_base + r) * XPAD;
            uint32_t bh0 = *(const uint32_t*)(xhi + xb + kg);
            uint32_t bh1 = *(const uint32_t*)(xhi + xb + kg + 8);
            uint32_t bl0 = *(const uint32_t*)(xlo + xb + kg);
            uint32_t bl1 = *(const uint32_t*)(xlo + xb + kg + 8);

            mma16816(acc, ah0, ah1, ah2, ah3, bh0, bh1);   // Whi*xhi
            mma16816(acc, ah0, ah1, ah2, ah3, bl0, bl1);   // Whi*xlo
            mma16816(acc, al0, al1, al2, al3, bh0, bh1);   // Wlo*xhi
        }
        __syncthreads();
    }

    // reduce K halves: kh=1 warps publish, kh=0 warps add
    if (kh == 1) {
        float* dst = red + (quad * 32 + lane) * 4;
        dst[0] = acc[0]; dst[1] = acc[1]; dst[2] = acc[2]; dst[3] = acc[3];
    }
    __syncthreads();
    if (kh == 0) {
        const float* srcv = red + (quad * 32 + lane) * 4;
        acc[0] += srcv[0]; acc[1] += srcv[1]; acc[2] += srcv[2]; acc[3] += srcv[3];
        // write quadrant to g4 [32 rows][17]
        int row0 = mrow_base + r;
        int col = nb_base + q4 * 2;
        g4[row0 * 17 + col]       = acc[0];
        g4[row0 * 17 + col + 1]   = acc[1];
        g4[(row0 + 8) * 17 + col]     = acc[2];
        g4[(row0 + 8) * 17 + col + 1] = acc[3];
    }
    __syncthreads();

    // pointwise: 8 units x 16 batches = 128 pairs
    if (tid < 128) {
        int unitloc = tid >> 4, b = tid & 15;
        int lr = unitloc * 4;
        int nrb = blockIdx.x * L_ROWS + lr;
        float gi = g4[(lr + 0) * 17 + b] + g_pb[nrb + 0];
        float gf = g4[(lr + 1) * 17 + b] + g_pb[nrb + 1];
        float gg = g4[(lr + 2) * 17 + b] + g_pb[nrb + 2];
        float go = g4[(lr + 3) * 17 + b] + g_pb[nrb + 3];
        int j = blockIdx.x * 8 + unitloc;
        float si = 1.f / (1.f + expf(-gi));
        float sf = 1.f / (1.f + expf(-gf));
        float so = 1.f / (1.f + expf(-go));
        float cc = sf * g_c[b * HH + j] + si * tanhf(gg);
        g_c[b * HH + j] = cc;
        float h = so * tanhf(cc);
        g_h[cur][b * HH + j] = h;
        g_h16[b * HH + j] = __float2half(h);
    }
}

// ---------------------------------------------------------------------
// K2: fp16 HMMA logits GEMM + epilogue + exact fp32 argmax rescue (R3, unchanged)
__global__ void __launch_bounds__(K2_THREADS)
k_logits(int t, const float* __restrict__ Wlin, const float* __restrict__ blin,
         float* __restrict__ out) {
    extern __shared__ char sm[];
    const uint32_t smem_base = smem_u32(sm);
    __half* h_s   = (__half*)(sm + H_OFF);
    float*  log_s = (float*)(sm + LOG_OFF);
    float*  thr_s = (float*)(sm + THR_OFF);
    int*    cnt_s = (int*)(sm + CNT_OFF);
    int*    cand_s = (int*)(sm + CAND_OFF);

    const int tid = threadIdx.x, warp = tid >> 5, lane = tid & 31;
    const int cur = (t + 1) & 1;
    const int r = lane >> 2, q4 = lane & 3;

    if (tid == 0) *cnt_s = 0;

#pragma unroll
    for (int q = 0; q < 8; q++) {
        int i = tid + q * 256;
        int b = i >> 7, k8 = i & 127;
        float4 v = *(const float4*)(g_h16 + (size_t)b * HH + k8 * 8);
        *(float4*)(h_s + b * HPAD + k8 * 8) = v;
    }

    const size_t wrow_base = (size_t)blockIdx.x * K2_ROWS * HH;
#pragma unroll
    for (int qq = 0; qq < 4; qq++) {
        int i = tid + qq * 256;
        int row = i >> 3, col16 = i & 7;
        CP16(smem_base + W0_OFF + (uint32_t)(row * WPAD + col16 * 8) * 2,
             g_W16 + wrow_base + (size_t)row * HH + col16 * 8);
    }
    CP_COMMIT();

    float acc0[4] = {0.f, 0.f, 0.f, 0.f};
    float acc1[4] = {0.f, 0.f, 0.f, 0.f};

    for (int c = 0; c < NCHUNK; c++) {
        if (c + 1 < NCHUNK) {
            uint32_t wb_off = ((c + 1) & 1) ? W1_OFF : W0_OFF;
#pragma unroll
            for (int qq = 0; qq < 4; qq++) {
                int i = tid + qq * 256;
                int row = i >> 3, col16 = i & 7;
                CP16(smem_base + wb_off + (uint32_t)(row * WPAD + col16 * 8) * 2,
                     g_W16 + wrow_base + (size_t)row * HH + (c + 1) * 64 + col16 * 8);
            }
            CP_COMMIT();
            CP_WAIT1();
        } else {
            CP_WAIT0();
        }
        __syncthreads();

        const __half* wb = (const __half*)(sm + ((c & 1) ? W1_OFF : W0_OFF));
        const int kbase = c * 64;
#pragma unroll
        for (int ks = 0; ks < 4; ks++) {
            int k0 = ks * 16 + q4 * 2;
            uint32_t a0 = *(const uint32_t*)(wb + (warp * 16 + r) * WPAD + k0);
            uint32_t a1 = *(const uint32_t*)(wb + (warp * 16 + r + 8) * WPAD + k0);
            uint32_t a2 = *(const uint32_t*)(wb + (warp * 16 + r) * WPAD + k0 + 8);
            uint32_t a3 = *(const uint32_t*)(wb + (warp * 16 + r + 8) * WPAD + k0 + 8);
            int kg = kbase + k0;
            uint32_t b00 = *(const uint32_t*)(h_s + r * HPAD + kg);
            uint32_t b01 = *(const uint32_t*)(h_s + r * HPAD + kg + 8);
            uint32_t b10 = *(const uint32_t*)(h_s + (r + 8) * HPAD + kg);
            uint32_t b11 = *(const uint32_t*)(h_s + (r + 8) * HPAD + kg + 8);
            mma16816(acc0, a0, a1, a2, a3, b00, b01);
            mma16816(acc1, a0, a1, a2, a3, b10, b11);
        }
        __syncthreads();
    }

    {
        const int rbase = warp * 16 + r;
        const float bl0 = blin[blockIdx.x * K2_ROWS + rbase];
        const float bl1 = blin[blockIdx.x * K2_ROWS + rbase + 8];
        const int c0 = q4 * 2;
        log_s[rbase * LPAD + c0]           = acc0[0] + bl0;
        log_s[rbase * LPAD + c0 + 1]       = acc0[1] + bl0;
        log_s[(rbase + 8) * LPAD + c0]     = acc0[2] + bl1;
        log_s[(rbase + 8) * LPAD + c0 + 1] = acc0[3] + bl1;
        log_s[rbase * LPAD + c0 + 8]       = acc1[0] + bl0;
        log_s[rbase * LPAD + c0 + 9]       = acc1[1] + bl0;
        log_s[(rbase + 8) * LPAD + c0 + 8] = acc1[2] + bl1;
        log_s[(rbase + 8) * LPAD + c0 + 9] = acc1[3] + bl1;
    }
    __syncthreads();

#pragma unroll
    for (int i = 0; i < 8; i++) {
        int idx = tid + i * 256;
        int row = idx & 127, b = idx >> 7;
        out[(size_t)b * TT * VV + (size_t)t * VV + blockIdx.x * K2_ROWS + row] =
            log_s[row * LPAD + b];
    }

    {
        int b = 2 * warp + (lane >> 4);
        int l = lane & 15;
        float s = 0.f, m = -1e30f;
#pragma unroll
        for (int rr = 0; rr < 8; rr++) {
            float v = log_s[(l * 8 + rr) * LPAD + b];
            s += expf(v);
            m = fmaxf(m, v);
        }
#pragma unroll
        for (int off = 8; off; off >>= 1) {
            s += __shfl_xor_sync(0xFFFFFFFFu, s, off);
            m = fmaxf(m, __shfl_xor_sync(0xFFFFFFFFu, m, off));
        }
        if (l == 0) {
            g_pexp[t][b][blockIdx.x] = s;
            unsigned fm = ford(m);
            unsigned old = atomicMax(&g_approx[cur][b], fm);
            unsigned L = old > fm ? old : fm;
            thr_s[b] = funord(L) - TAU;
        }
    }
    __syncthreads();

#pragma unroll
    for (int i = 0; i < 8; i++) {
        int idx = tid + i * 256;
        int row = idx & 127, b = idx >> 7;
        if (log_s[row * LPAD + b] >= thr_s[b]) {
            int slot = atomicAdd(cnt_s, 1);
            if (slot < 128) cand_s[slot] = ((blockIdx.x * K2_ROWS + row) << 4) | b;
        }
    }
    __syncthreads();

    int n = *cnt_s; if (n > 128) n = 128;
    for (int e = warp; e < n; e += 8) {
        int pk = cand_s[e];
        int rr = pk >> 4, b = pk & 15;
        const float4* Wr = (const float4*)(Wlin + (size_t)rr * HH);
        const float4* hr = (const float4*)(g_h[cur] + b * HH);
        float acc = 0.f;
#pragma unroll
        for (int qq = 0; qq < 8; qq++) {
            float4 w = Wr[lane + qq * 32];
            float4 h = hr[lane + qq * 32];
            acc += w.x * h.x + w.y * h.y + w.z * h.z + w.w * h.w;
        }
#pragma unroll
        for (int off = 16; off; off >>= 1) acc += __shfl_xor_sync(0xFFFFFFFFu, acc, off);
        if (lane == 0) {
            float ex = acc + blin[rr];
            unsigned long long pkd =
                ((unsigned long long)ford(ex) << 32) | (unsigned)(~(unsigned)rr);
            atomicMax(&g_amax[cur][b], pkd);
        }
    }
}

// ---------------------------------------------------------------------
__global__ void k_final(float* __restrict__ out) {
    const int t = blockIdx.x >> 4;
    const int b = blockIdx.x & 15;
    __shared__ float red[256];
    float s = 0.f;
    for (int i = threadIdx.x; i < K2_BLOCKS; i += 256) s += g_pexp[t][b][i];
    red[threadIdx.x] = s;
    __syncthreads();
    for (int off = 128; off; off >>= 1) {
        if (threadIdx.x < off) red[threadIdx.x] += red[threadIdx.x + off];
        __syncthreads();
    }
    const float lse = logf(red[0]);
    float* p = out + (size_t)b * TT * VV + (size_t)t * VV;
    for (int i = threadIdx.x; i < VV / 4; i += 256) {
        float4 v = *(float4*)(p + i * 4);
        v.x -= lse; v.y -= lse; v.z -= lse; v.w -= lse;
        *(float4*)(p + i * 4) = v;
    }
}

__global__ void k_hc(float* __restrict__ out) {
    int i = blockIdx.x * blockDim.x + threadIdx.x;
    if (i < BB * HH) {
        out[(size_t)BB * TT * VV + i]           = g_h[0][i];
        out[(size_t)BB * TT * VV + BB * HH + i] = g_c[i];
    }
}

// ---------------------------------------------------------------------
extern "C" void kernel_launch(void* const* d_in, const int* in_sizes, int n_in,
                              void* d_out, int out_size) {
    const float* h0   = (const float*)d_in[1];
    const float* c0   = (const float*)d_in[2];
    const float* emb  = (const float*)d_in[3];
    const float* Wih  = (const float*)d_in[4];
    const float* Whh  = (const float*)d_in[5];
    const float* bih  = (const float*)d_in[6];
    const float* bhh  = (const float*)d_in[7];
    const float* Wlin = (const float*)d_in[8];
    const float* blin = (const float*)d_in[9];
    float* out = (float*)d_out;

    cudaFuncSetAttribute(k_logits, cudaFuncAttributeMaxDynamicSharedMemorySize, K2_SMEM);
    cudaFuncSetAttribute(k_lstm3, cudaFuncAttributeMaxDynamicSharedMemorySize, L_SMEM);

    k_init<<<(BB * HH + 255) / 256, 256>>>(h0, c0, bih, bhh);
    k_cvt<<<(int)((size_t)VV * HH / 8 / 256), 256>>>(Wlin);
    k_cvt2<<<(int)((size_t)4 * HH * KK / 8 / 256), 256>>>(Wih, Whh);
    for (int t = 0; t < TT; t++) {
        k_xsplit<<<32, 256>>>(t, emb);
        k_lstm3<<<L_BLOCKS, L_THREADS, L_SMEM>>>(t);
        k_logits<<<K2_BLOCKS, K2_THREADS, K2_SMEM>>>(t, Wlin, blin, out);
    }
    k_final<<<TT * BB, 256>>>(out);
    k_hc<<<(BB * HH + 255) / 256, 256>>>(out);
}